// round 15
// baseline (speedup 1.0000x reference)
#include <cuda_runtime.h>
#include <cuda_fp16.h>
#include <math.h>
#include <stdint.h>

#define N_NODES  50000
#define N_EDGES  800000
#define N_GRAPHS 2048
#define NE_TOT   (N_EDGES + N_NODES)
#define F0 78
#define F1 78
#define F2 156
#define F3 312

#define SCAN_NB ((N_NODES + 255) / 256)   // 196

// padded stride (elements): multiple of 16
#define KP16(K) (((K) + 15) & ~15)
#define FP0 KP16(F0)    // 80
#define FP2 KP16(F2)    // 160
#define FP3 KP16(F3)    // 320

// weight transpose offsets ([N][KP16] layout, fp16)
#define OW1  0
#define OW2  (OW1 + F1 * KP16(F0))
#define OW3  (OW2 + F2 * KP16(F1))
#define OWG1 (OW3 + F3 * KP16(F2))
#define OWG2 (OWG1 + 1024 * KP16(F3))
#define OWF1 (OWG2 + 128 * 1024)
#define OWF2 (OWF1 + 1024 * 128)
#define WTOT (OWF2 + 512 * 1024)

#define SEG_EDGE  N_EDGES
#define SEG_BATCH (SEG_EDGE + N_NODES)
#define NW1  (F0 * F1)
#define NW2  (F1 * F2)
#define NW3  (F2 * F3)
#define NWG1 (F3 * 1024)
#define NWG2 (1024 * 128)
#define NWF1 (128 * 1024)
#define NWF2 (1024 * 512)
#define SEG_W1  (SEG_BATCH + NW1)
#define SEG_W2  (SEG_W1 + NW2)
#define SEG_W3  (SEG_W2 + NW3)
#define SEG_WG1 (SEG_W3 + NWG1)
#define SEG_WG2 (SEG_WG1 + NWG2)
#define SEG_WF1 (SEG_WG2 + NWF1)
#define SEG_WF2 (SEG_WF1 + NWF2)
#define SEG_XP  (SEG_WF2 + N_NODES * F0)
#define PREP_TOT SEG_XP

struct EdgeRec { int src; float w; };

// ---------------- scratch (device globals; zero-initialized -> fp16 +0.0 pads) ------------
__device__ __align__(16) uint16_t g_xp[N_NODES * FP0];   // padded x (fp16)
__device__ __align__(16) uint16_t g_a [N_NODES * FP2];   // agg output (fp16) = GEMM A
__device__ __align__(16) uint16_t g_w [WTOT];            // weights transposed (fp16)
__device__ __align__(16) uint16_t g_y1[N_NODES * FP0];
__device__ __align__(16) uint16_t g_y2[N_NODES * FP2];
__device__ __align__(16) uint16_t g_y3[N_NODES * FP3];
__device__ __align__(16) uint16_t g_p [N_GRAPHS * FP3];
__device__ __align__(16) uint16_t g_m1[N_GRAPHS * 1024];
__device__ __align__(16) uint16_t g_m2[N_GRAPHS * 1024];
__device__ int     g_count[N_NODES];
__device__ int     g_rowptr[N_NODES + 1];
__device__ int     g_cursor[N_NODES];
__device__ float   g_dinv[N_NODES];
__device__ int     g_bsum[SCAN_NB];
__device__ EdgeRec g_edge[NE_TOT];
__device__ int     g_batch[N_NODES];
__device__ int     g_gstart[N_GRAPHS + 1];

__device__ __forceinline__ uint16_t f2h(float x) {
    return __half_as_ushort(__float2half_rn(x));
}

// pack two floats into fp16x2 bits
__device__ __forceinline__ uint32_t f2h2(float lo, float hi) {
    uint16_t a = __half_as_ushort(__float2half_rn(lo));
    uint16_t b = __half_as_ushort(__float2half_rn(hi));
    return ((uint32_t)b << 16) | a;
}

// ---------------- fused prep: hist, batch, weights, x pad ---------
__device__ __forceinline__ void wcvt_one(const float* W, int off, int K, int N,
                                         int kp16, int idx) {
    int k = idx / N, n = idx % N;
    g_w[(size_t)off + (size_t)n * kp16 + k] = f2h(W[idx]);
}

__global__ void prep_kernel(const int* __restrict__ ei, const int* __restrict__ batch,
                            const float* __restrict__ x,
                            const float* __restrict__ W1, const float* __restrict__ W2,
                            const float* __restrict__ W3, const float* __restrict__ Wg1,
                            const float* __restrict__ Wg2, const float* __restrict__ Wf1,
                            const float* __restrict__ Wf2)
{
    int idx = blockIdx.x * blockDim.x + threadIdx.x;
    if (idx >= PREP_TOT) return;
    if (idx < SEG_EDGE) {
        atomicAdd(&g_count[ei[N_EDGES + idx]], 1);
    } else if (idx < SEG_BATCH) {
        int i = idx - SEG_EDGE;
        g_batch[i] = batch[i];
    } else if (idx < SEG_W1)  wcvt_one(W1,  OW1,  F0,   F1,   KP16(F0),  idx - SEG_BATCH);
    else if (idx < SEG_W2)    wcvt_one(W2,  OW2,  F1,   F2,   KP16(F1),  idx - SEG_W1);
    else if (idx < SEG_W3)    wcvt_one(W3,  OW3,  F2,   F3,   KP16(F2),  idx - SEG_W2);
    else if (idx < SEG_WG1)   wcvt_one(Wg1, OWG1, F3,   1024, KP16(F3),  idx - SEG_W3);
    else if (idx < SEG_WG2)   wcvt_one(Wg2, OWG2, 1024, 128,  1024,      idx - SEG_WG1);
    else if (idx < SEG_WF1)   wcvt_one(Wf1, OWF1, 128,  1024, 128,       idx - SEG_WG2);
    else if (idx < SEG_WF2)   wcvt_one(Wf2, OWF2, 1024, 512,  1024,      idx - SEG_WF1);
    else {
        int i = idx - SEG_WF2;
        int n = i / F0, c = i % F0;
        g_xp[(size_t)n * FP0 + c] = f2h(x[i]);     // pads stay 0 (= fp16 +0.0)
    }
}

// ---------------- scan phase 1: block sums of deg = count+1 ----------------
__global__ void scan_p1_kernel() {
    __shared__ int sh[256];
    int t = threadIdx.x;
    int i = blockIdx.x * 256 + t;
    int v = (i < N_NODES) ? g_count[i] + 1 : 0;
    sh[t] = v;
    __syncthreads();
    for (int o = 128; o; o >>= 1) {
        if (t < o) sh[t] += sh[t + o];
        __syncthreads();
    }
    if (t == 0) g_bsum[blockIdx.x] = sh[0];
}

// ---------------- scan phase 2+3 fused ----------------
__global__ void scan_p3_kernel() {
    __shared__ int sb[256];
    __shared__ int sh[256];
    int t = threadIdx.x;

    sb[t] = (t < SCAN_NB) ? g_bsum[t] : 0;
    __syncthreads();
    for (int off = 1; off < 256; off <<= 1) {
        int u = (t >= off) ? sb[t - off] : 0;
        __syncthreads();
        sb[t] += u;
        __syncthreads();
    }
    int boff = (blockIdx.x == 0) ? 0 : sb[blockIdx.x - 1];
    if (blockIdx.x == 0 && t == 0) g_rowptr[N_NODES] = sb[SCAN_NB - 1];

    int i = blockIdx.x * 256 + t;
    int v = (i < N_NODES) ? g_count[i] + 1 : 0;
    sh[t] = v;
    __syncthreads();
    for (int off = 1; off < 256; off <<= 1) {
        int u = (t >= off) ? sh[t - off] : 0;
        __syncthreads();
        sh[t] += u;
        __syncthreads();
    }
    if (i < N_NODES) {
        int r = boff + sh[t] - v;
        g_rowptr[i] = r;
        g_cursor[i] = r;
        g_dinv[i] = rsqrtf((float)v);
        g_count[i] = 0;
    }
}

// ---------------- fused: CSR fill (reads ei directly) + gstart ----------------
__global__ void fill_kernel(const int* __restrict__ ei) {
    int t = blockIdx.x * blockDim.x + threadIdx.x;
    if (t < N_EDGES) {
        int s = ei[t];
        int d = ei[N_EDGES + t];
        int p = atomicAdd(&g_cursor[d], 1);
        EdgeRec r;
        r.src = s;
        r.w = g_dinv[s] * g_dinv[d];
        g_edge[p] = r;
    } else if (t < NE_TOT) {
        int i = t - N_EDGES;
        int p = atomicAdd(&g_cursor[i], 1);
        float di = g_dinv[i];
        EdgeRec r;
        r.src = i;
        r.w = di * di;
        g_edge[p] = r;
    } else if (t <= NE_TOT + N_NODES) {
        int i = t - NE_TOT;
        if (i == 0) {
            for (int g = 0; g <= g_batch[0]; g++) g_gstart[g] = 0;
        } else if (i == N_NODES) {
            for (int g = g_batch[N_NODES - 1] + 1; g <= N_GRAPHS; g++) g_gstart[g] = N_NODES;
        } else {
            int b0 = g_batch[i - 1], b1 = g_batch[i];
            for (int g = b0 + 1; g <= b1; g++) g_gstart[g] = i;
        }
    }
}

// ---------------- GCN aggregation: warp/node, 4-edge software pipeline ----------------
// V = padded row width in 4-half chunks (FP/4): 20 (FP0), 40 (FP2)
template <int V>
__global__ void __launch_bounds__(256) agg_kernel_h(
    const uint2* __restrict__ xp, uint2* __restrict__ aout)
{
    constexpr int NC = (V + 31) / 32;
    int node = blockIdx.x * 8 + threadIdx.y;
    if (node >= N_NODES) return;
    int lane = threadIdx.x;
    int k0 = g_rowptr[node], k1 = g_rowptr[node + 1];

    float4 acc0[NC], acc1[NC];
    #pragma unroll
    for (int i = 0; i < NC; i++) {
        acc0[i] = make_float4(0.f, 0.f, 0.f, 0.f);
        acc1[i] = make_float4(0.f, 0.f, 0.f, 0.f);
    }

    const int2* ep = (const int2*)g_edge;

    int k = k0;
    for (; k + 4 <= k1; k += 4) {
        int2 e[4];
        #pragma unroll
        for (int j = 0; j < 4; j++) e[j] = ep[k + j];
        #pragma unroll
        for (int i = 0; i < NC; i++) {
            int f = i * 32 + lane;
            if (f < V) {
                uint2 u[4];
                #pragma unroll
                for (int j = 0; j < 4; j++)           // 4 independent gathers in flight
                    u[j] = xp[(size_t)e[j].x * V + f];
                #pragma unroll
                for (int j = 0; j < 4; j++) {
                    float wj = __int_as_float(e[j].y);
                    float2 v01 = __half22float2(*(const __half2*)&u[j].x);
                    float2 v23 = __half22float2(*(const __half2*)&u[j].y);
                    float4& acc = (j & 1) ? acc1[i] : acc0[i];
                    acc.x = fmaf(v01.x, wj, acc.x);
                    acc.y = fmaf(v01.y, wj, acc.y);
                    acc.z = fmaf(v23.x, wj, acc.z);
                    acc.w = fmaf(v23.y, wj, acc.w);
                }
            }
        }
    }
    for (; k < k1; k++) {
        int2 er = ep[k];
        float w = __int_as_float(er.y);
        const uint2* row = xp + (size_t)er.x * V;
        #pragma unroll
        for (int i = 0; i < NC; i++) {
            int f = i * 32 + lane;
            if (f < V) {
                uint2 u = row[f];
                float2 v01 = __half22float2(*(const __half2*)&u.x);
                float2 v23 = __half22float2(*(const __half2*)&u.y);
                acc0[i].x = fmaf(v01.x, w, acc0[i].x);
                acc0[i].y = fmaf(v01.y, w, acc0[i].y);
                acc0[i].z = fmaf(v23.x, w, acc0[i].z);
                acc0[i].w = fmaf(v23.y, w, acc0[i].w);
            }
        }
    }

    #pragma unroll
    for (int i = 0; i < NC; i++) {
        int f = i * 32 + lane;
        if (f < V) {
            uint2 o;
            o.x = f2h2(acc0[i].x + acc1[i].x, acc0[i].y + acc1[i].y);
            o.y = f2h2(acc0[i].z + acc1[i].z, acc0[i].w + acc1[i].w);
            aout[(size_t)node * V + f] = o;
        }
    }
}

// ---------------- fp16 tensor-core GEMM ----------------
#define BM 128
#define BN 64

__device__ __forceinline__ void mma_f16(float* c, const uint32_t* a, const uint32_t* b) {
    asm volatile(
        "mma.sync.aligned.m16n8k16.row.col.f32.f16.f16.f32 "
        "{%0,%1,%2,%3}, {%4,%5,%6,%7}, {%8,%9}, {%0,%1,%2,%3};\n"
        : "+f"(c[0]), "+f"(c[1]), "+f"(c[2]), "+f"(c[3])
        : "r"(a[0]), "r"(a[1]), "r"(a[2]), "r"(a[3]), "r"(b[0]), "r"(b[1]));
}

// A: [M][K2P] uint32 (half pairs, pad=0). B: [N][K2P] uint32 (half pairs, pad=0).
// C: fp16, stride NP halves.
__global__ void __launch_bounds__(256) h_gemm_kernel(
    const uint32_t* __restrict__ A32, const uint32_t* __restrict__ B32,
    const float* __restrict__ bias, uint32_t* __restrict__ C32,
    int M, int N, int NP, int K, int K2P, int relu)
{
    __shared__ uint32_t sA[BM][9];   // 8 half-pairs + pad
    __shared__ uint32_t sB[BN][9];

    int tid = threadIdx.x;
    int warp = tid >> 5, lane = tid & 31;
    int wm = warp >> 1;
    int wn = warp & 1;
    int g = lane >> 2, tg = lane & 3;
    int rowBase = blockIdx.y * BM;
    int colBase = blockIdx.x * BN;

    float acc[2][4][4];
    #pragma unroll
    for (int mt = 0; mt < 2; mt++)
        #pragma unroll
        for (int nt = 0; nt < 4; nt++)
            #pragma unroll
            for (int i = 0; i < 4; i++) acc[mt][nt][i] = 0.0f;

    // loads: A — 2 threads/row, uint4 (8 halves) each; B — threads 0..127, 2/row
    int rowA = tid >> 1;
    int halfA = tid & 1;
    int nB = (tid & 127) >> 1;
    int halfB = tid & 1;
    bool doB = tid < 128;

    bool aok = (rowBase + rowA) < M;
    bool bok = doB && (colBase + nB) < N;
    const uint32_t* Ap = A32 + (size_t)(rowBase + rowA) * K2P + halfA * 4;
    const uint32_t* Bp = B32 + (size_t)(colBase + nB) * K2P + halfB * 4;

    const uint4 z4 = make_uint4(0u, 0u, 0u, 0u);
    uint4 ra, rb;
    ra = aok ? *(const uint4*)(Ap) : z4;
    rb = bok ? *(const uint4*)(Bp) : z4;

    for (int k0 = 0; k0 < K; k0 += 16) {
        __syncthreads();
        int ka = halfA * 4;
        sA[rowA][ka] = ra.x; sA[rowA][ka + 1] = ra.y;
        sA[rowA][ka + 2] = ra.z; sA[rowA][ka + 3] = ra.w;
        if (doB) {
            int kb = halfB * 4;
            sB[nB][kb] = rb.x; sB[nB][kb + 1] = rb.y;
            sB[nB][kb + 2] = rb.z; sB[nB][kb + 3] = rb.w;
        }
        __syncthreads();
        if (k0 + 16 < K) {
            int kp = (k0 + 16) >> 1;
            ra = aok ? *(const uint4*)(Ap + kp) : z4;
            rb = bok ? *(const uint4*)(Bp + kp) : z4;
        }

        uint32_t af[2][4];
        #pragma unroll
        for (int mt = 0; mt < 2; mt++) {
            int r0 = wm * 32 + mt * 16 + g;
            af[mt][0] = sA[r0][tg];     af[mt][1] = sA[r0 + 8][tg];
            af[mt][2] = sA[r0][tg + 4]; af[mt][3] = sA[r0 + 8][tg + 4];
        }
        uint32_t bf[4][2];
        #pragma unroll
        for (int nt = 0; nt < 4; nt++) {
            int n0 = wn * 32 + nt * 8 + g;
            bf[nt][0] = sB[n0][tg]; bf[nt][1] = sB[n0][tg + 4];
        }
        #pragma unroll
        for (int mt = 0; mt < 2; mt++)
            #pragma unroll
            for (int nt = 0; nt < 4; nt++)
                mma_f16(acc[mt][nt], af[mt], bf[nt]);
    }

    #pragma unroll
    for (int mt = 0; mt < 2; mt++) {
        int r0 = rowBase + wm * 32 + mt * 16 + g;
        #pragma unroll
        for (int nt = 0; nt < 4; nt++) {
            int c0 = colBase + wn * 32 + nt * 8 + tg * 2;
            #pragma unroll
            for (int half = 0; half < 2; half++) {
                int r = r0 + half * 8;
                if (r >= M || c0 >= N) continue;
                float v0 = acc[mt][nt][half * 2 + 0] + bias[c0];
                float v1 = acc[mt][nt][half * 2 + 1] + bias[c0 + 1];
                if (relu) { v0 = fmaxf(v0, 0.0f); v1 = fmaxf(v1, 0.0f); }
                C32[((size_t)r * NP + c0) >> 1] = f2h2(v0, v1);
            }
        }
    }
}

// ---------------- segmented global max pool (fp16 in/out) ----------------
__global__ void pool_kernel(const uint16_t* __restrict__ y)
{
    int grp = blockIdx.x * blockDim.y + threadIdx.y;
    if (grp >= N_GRAPHS) return;
    int c = blockIdx.y * 32 + threadIdx.x;
    if (c >= F3) return;
    int s = g_gstart[grp], e = g_gstart[grp + 1];
    float m = 0.0f;
    for (int i = s; i < e; i++)
        m = fmaxf(m, __half2float(__ushort_as_half(y[(size_t)i * FP3 + c])));
    g_p[(size_t)grp * FP3 + c] = f2h(m);
}

// ---------------- final 512 -> 1 dot + sigmoid ----------------
__global__ void final_kernel(const float* __restrict__ Wo,
                             const float* __restrict__ bo, float* __restrict__ out)
{
    int row = blockIdx.x * blockDim.y + threadIdx.y;
    if (row >= N_GRAPHS) return;
    int lane = threadIdx.x;
    float s = 0.0f;
    for (int k = lane; k < 512; k += 32)
        s = fmaf(__half2float(__ushort_as_half(g_m2[(size_t)row * 512 + k])), Wo[k], s);
    #pragma unroll
    for (int o = 16; o; o >>= 1) s += __shfl_xor_sync(0xFFFFFFFFu, s, o);
    if (lane == 0) out[row] = 1.0f / (1.0f + expf(-(s + bo[0])));
}

// ---------------- launch ----------------
extern "C" void kernel_launch(void* const* d_in, const int* in_sizes, int n_in,
                              void* d_out, int out_size)
{
    const float* x     = (const float*)d_in[0];
    const int*   ei    = (const int*)d_in[1];
    const int*   batch = (const int*)d_in[2];
    const float* W1 = (const float*)d_in[3];  const float* b1 = (const float*)d_in[4];
    const float* W2 = (const float*)d_in[5];  const float* b2 = (const float*)d_in[6];
    const float* W3 = (const float*)d_in[7];  const float* b3 = (const float*)d_in[8];
    const float* Wg1 = (const float*)d_in[9];  const float* bg1 = (const float*)d_in[10];
    const float* Wg2 = (const float*)d_in[11]; const float* bg2 = (const float*)d_in[12];
    const float* Wf1 = (const float*)d_in[13]; const float* bf1 = (const float*)d_in[14];
    const float* Wf2 = (const float*)d_in[15]; const float* bf2 = (const float*)d_in[16];
    const float* Wo  = (const float*)d_in[17]; const float* bo  = (const float*)d_in[18];
    float* out = (float*)d_out;

    uint16_t *xp, *a, *w, *y1, *y2, *y3, *p, *m1, *m2;
    cudaGetSymbolAddress((void**)&xp, g_xp);
    cudaGetSymbolAddress((void**)&a,  g_a);
    cudaGetSymbolAddress((void**)&w,  g_w);
    cudaGetSymbolAddress((void**)&y1, g_y1);
    cudaGetSymbolAddress((void**)&y2, g_y2);
    cudaGetSymbolAddress((void**)&y3, g_y3);
    cudaGetSymbolAddress((void**)&p,  g_p);
    cudaGetSymbolAddress((void**)&m1, g_m1);
    cudaGetSymbolAddress((void**)&m2, g_m2);

    // preprocessing: 4 launches
    prep_kernel<<<(PREP_TOT + 255) / 256, 256>>>(ei, batch, x, W1, W2, W3, Wg1, Wg2, Wf1, Wf2);
    scan_p1_kernel<<<SCAN_NB, 256>>>();
    scan_p3_kernel<<<SCAN_NB, 256>>>();
    fill_kernel<<<(NE_TOT + N_NODES + 1 + 255) / 256, 256>>>(ei);

    auto gemm = [&](const uint16_t* A, int woff, const float* bias, uint16_t* C,
                    int M, int N, int NP, int K, int K2P, int relu) {
        dim3 grid((N + BN - 1) / BN, (M + BM - 1) / BM);
        h_gemm_kernel<<<grid, 256>>>((const uint32_t*)A, (const uint32_t*)(w + woff),
                                     bias, (uint32_t*)C, M, N, NP, K, K2P, relu);
    };
    dim3 cb(32, 8);

    // layer 1: gather xp (V=20) -> a -> GEMM -> y1 (pad 80)
    agg_kernel_h<20><<<(N_NODES + 7) / 8, cb>>>((const uint2*)xp, (uint2*)a);
    gemm(a, OW1, b1, y1, N_NODES, F1, FP0, F0, FP0 / 2, 1);
    // layer 2: gather y1 (V=20) -> a -> GEMM -> y2 (pad 160)
    agg_kernel_h<20><<<(N_NODES + 7) / 8, cb>>>((const uint2*)y1, (uint2*)a);
    gemm(a, OW2, b2, y2, N_NODES, F2, FP2, F1, FP0 / 2, 1);
    // layer 3: gather y2 (V=40) -> a -> GEMM -> y3 (pad 320)
    agg_kernel_h<40><<<(N_NODES + 7) / 8, cb>>>((const uint2*)y2, (uint2*)a);
    gemm(a, OW3, b3, y3, N_NODES, F3, FP3, F2, FP2 / 2, 1);

    // pool
    pool_kernel<<<dim3((N_GRAPHS + 7) / 8, (F3 + 31) / 32), cb>>>(y3);

    // MLP head (all fp16 storage, fp32 accumulate)
    gemm(p,  OWG1, bg1, m1, N_GRAPHS, 1024, 1024, F3,   FP3 / 2,  1);
    gemm(m1, OWG2, bg2, m2, N_GRAPHS, 128,  128,  1024, 512,      0);
    gemm(m2, OWF1, bf1, m1, N_GRAPHS, 1024, 1024, 128,  64,       1);
    gemm(m1, OWF2, bf2, m2, N_GRAPHS, 512,  512,  1024, 512,      1);
    final_kernel<<<(N_GRAPHS + 7) / 8, cb>>>(Wo, bo, out);
}

// round 16
// speedup vs baseline: 1.0888x; 1.0888x over previous
#include <cuda_runtime.h>
#include <cuda_fp16.h>
#include <math.h>
#include <stdint.h>

#define N_NODES  50000
#define N_EDGES  800000
#define N_GRAPHS 2048
#define NE_TOT   (N_EDGES + N_NODES)
#define F0 78
#define F1 78
#define F2 156
#define F3 312

#define SCAN_NB ((N_NODES + 255) / 256)   // 196

// padded stride (elements): multiple of 16
#define KP16(K) (((K) + 15) & ~15)
#define FP0 KP16(F0)    // 80
#define FP2 KP16(F2)    // 160
#define FP3 KP16(F3)    // 320

// weight transpose offsets ([N][KP16] layout, fp16)
#define OW1  0
#define OW2  (OW1 + F1 * KP16(F0))
#define OW3  (OW2 + F2 * KP16(F1))
#define OWG1 (OW3 + F3 * KP16(F2))
#define OWG2 (OWG1 + 1024 * KP16(F3))
#define OWF1 (OWG2 + 128 * 1024)
#define OWF2 (OWF1 + 1024 * 128)
#define WTOT (OWF2 + 512 * 1024)

#define SEG_EDGE  N_EDGES
#define SEG_BATCH (SEG_EDGE + N_NODES)
#define NW1  (F0 * F1)
#define NW2  (F1 * F2)
#define NW3  (F2 * F3)
#define NWG1 (F3 * 1024)
#define NWG2 (1024 * 128)
#define NWF1 (128 * 1024)
#define NWF2 (1024 * 512)
#define SEG_W1  (SEG_BATCH + NW1)
#define SEG_W2  (SEG_W1 + NW2)
#define SEG_W3  (SEG_W2 + NW3)
#define SEG_WG1 (SEG_W3 + NWG1)
#define SEG_WG2 (SEG_WG1 + NWG2)
#define SEG_WF1 (SEG_WG2 + NWF1)
#define SEG_WF2 (SEG_WF1 + NWF2)
#define SEG_XP  (SEG_WF2 + N_NODES * F0)
#define PREP_TOT SEG_XP

struct EdgeRec { int src; float w; };

// ---------------- scratch (device globals; zero-initialized -> fp16 +0.0 pads) ------------
__device__ __align__(16) uint16_t g_xp[N_NODES * FP0];   // padded x (fp16)
__device__ __align__(16) uint16_t g_a [N_NODES * FP2];   // agg output (fp16) = GEMM A
__device__ __align__(16) uint16_t g_w [WTOT];            // weights transposed (fp16)
__device__ __align__(16) uint16_t g_y1[N_NODES * FP0];
__device__ __align__(16) uint16_t g_y2[N_NODES * FP2];
__device__ __align__(16) uint16_t g_y3[N_NODES * FP3];
__device__ __align__(16) uint16_t g_p [N_GRAPHS * FP3];
__device__ __align__(16) uint16_t g_m1[N_GRAPHS * 1024];
__device__ __align__(16) uint16_t g_m2[N_GRAPHS * 1024];
__device__ int     g_count[N_NODES];
__device__ int     g_rowptr[N_NODES + 1];
__device__ int     g_cursor[N_NODES];
__device__ float   g_dinv[N_NODES];
__device__ int     g_bsum[SCAN_NB];
__device__ EdgeRec g_edge[NE_TOT];
__device__ int     g_batch[N_NODES];
__device__ int     g_gstart[N_GRAPHS + 1];

__device__ __forceinline__ uint16_t f2h(float x) {
    return __half_as_ushort(__float2half_rn(x));
}

// pack two floats into fp16x2 bits
__device__ __forceinline__ uint32_t f2h2(float lo, float hi) {
    uint16_t a = __half_as_ushort(__float2half_rn(lo));
    uint16_t b = __half_as_ushort(__float2half_rn(hi));
    return ((uint32_t)b << 16) | a;
}

// ---------------- fused prep: hist, batch, weights, x pad ---------
__device__ __forceinline__ void wcvt_one(const float* W, int off, int K, int N,
                                         int kp16, int idx) {
    int k = idx / N, n = idx % N;
    g_w[(size_t)off + (size_t)n * kp16 + k] = f2h(W[idx]);
}

__global__ void prep_kernel(const int* __restrict__ ei, const int* __restrict__ batch,
                            const float* __restrict__ x,
                            const float* __restrict__ W1, const float* __restrict__ W2,
                            const float* __restrict__ W3, const float* __restrict__ Wg1,
                            const float* __restrict__ Wg2, const float* __restrict__ Wf1,
                            const float* __restrict__ Wf2)
{
    int idx = blockIdx.x * blockDim.x + threadIdx.x;
    if (idx >= PREP_TOT) return;
    if (idx < SEG_EDGE) {
        atomicAdd(&g_count[ei[N_EDGES + idx]], 1);
    } else if (idx < SEG_BATCH) {
        int i = idx - SEG_EDGE;
        g_batch[i] = batch[i];
    } else if (idx < SEG_W1)  wcvt_one(W1,  OW1,  F0,   F1,   KP16(F0),  idx - SEG_BATCH);
    else if (idx < SEG_W2)    wcvt_one(W2,  OW2,  F1,   F2,   KP16(F1),  idx - SEG_W1);
    else if (idx < SEG_W3)    wcvt_one(W3,  OW3,  F2,   F3,   KP16(F2),  idx - SEG_W2);
    else if (idx < SEG_WG1)   wcvt_one(Wg1, OWG1, F3,   1024, KP16(F3),  idx - SEG_W3);
    else if (idx < SEG_WG2)   wcvt_one(Wg2, OWG2, 1024, 128,  1024,      idx - SEG_WG1);
    else if (idx < SEG_WF1)   wcvt_one(Wf1, OWF1, 128,  1024, 128,       idx - SEG_WG2);
    else if (idx < SEG_WF2)   wcvt_one(Wf2, OWF2, 1024, 512,  1024,      idx - SEG_WF1);
    else {
        int i = idx - SEG_WF2;
        int n = i / F0, c = i % F0;
        g_xp[(size_t)n * FP0 + c] = f2h(x[i]);     // pads stay 0 (= fp16 +0.0)
    }
}

// ---------------- scan phase 1: block sums of deg = count+1 ----------------
__global__ void scan_p1_kernel() {
    __shared__ int sh[256];
    int t = threadIdx.x;
    int i = blockIdx.x * 256 + t;
    int v = (i < N_NODES) ? g_count[i] + 1 : 0;
    sh[t] = v;
    __syncthreads();
    for (int o = 128; o; o >>= 1) {
        if (t < o) sh[t] += sh[t + o];
        __syncthreads();
    }
    if (t == 0) g_bsum[blockIdx.x] = sh[0];
}

// ---------------- scan phase 2+3 fused ----------------
__global__ void scan_p3_kernel() {
    __shared__ int sb[256];
    __shared__ int sh[256];
    int t = threadIdx.x;

    sb[t] = (t < SCAN_NB) ? g_bsum[t] : 0;
    __syncthreads();
    for (int off = 1; off < 256; off <<= 1) {
        int u = (t >= off) ? sb[t - off] : 0;
        __syncthreads();
        sb[t] += u;
        __syncthreads();
    }
    int boff = (blockIdx.x == 0) ? 0 : sb[blockIdx.x - 1];
    if (blockIdx.x == 0 && t == 0) g_rowptr[N_NODES] = sb[SCAN_NB - 1];

    int i = blockIdx.x * 256 + t;
    int v = (i < N_NODES) ? g_count[i] + 1 : 0;
    sh[t] = v;
    __syncthreads();
    for (int off = 1; off < 256; off <<= 1) {
        int u = (t >= off) ? sh[t - off] : 0;
        __syncthreads();
        sh[t] += u;
        __syncthreads();
    }
    if (i < N_NODES) {
        int r = boff + sh[t] - v;
        g_rowptr[i] = r;
        g_cursor[i] = r;
        g_dinv[i] = rsqrtf((float)v);
        g_count[i] = 0;
    }
}

// ---------------- fused: CSR fill (reads ei directly) + gstart ----------------
__global__ void fill_kernel(const int* __restrict__ ei) {
    int t = blockIdx.x * blockDim.x + threadIdx.x;
    if (t < N_EDGES) {
        int s = ei[t];
        int d = ei[N_EDGES + t];
        int p = atomicAdd(&g_cursor[d], 1);
        EdgeRec r;
        r.src = s;
        r.w = g_dinv[s] * g_dinv[d];
        g_edge[p] = r;
    } else if (t < NE_TOT) {
        int i = t - N_EDGES;
        int p = atomicAdd(&g_cursor[i], 1);
        float di = g_dinv[i];
        EdgeRec r;
        r.src = i;
        r.w = di * di;
        g_edge[p] = r;
    } else if (t <= NE_TOT + N_NODES) {
        int i = t - NE_TOT;
        if (i == 0) {
            for (int g = 0; g <= g_batch[0]; g++) g_gstart[g] = 0;
        } else if (i == N_NODES) {
            for (int g = g_batch[N_NODES - 1] + 1; g <= N_GRAPHS; g++) g_gstart[g] = N_NODES;
        } else {
            int b0 = g_batch[i - 1], b1 = g_batch[i];
            for (int g = b0 + 1; g <= b1; g++) g_gstart[g] = i;
        }
    }
}

// ---------------- GCN aggregation: warp/node, simple loop (measured best) ----------------
// V = padded row width in 4-half chunks (FP/4): 20 (FP0), 40 (FP2)
template <int V>
__global__ void __launch_bounds__(256) agg_kernel_h(
    const uint2* __restrict__ xp, uint2* __restrict__ aout)
{
    constexpr int NC = (V + 31) / 32;
    int node = blockIdx.x * 8 + threadIdx.y;
    if (node >= N_NODES) return;
    int lane = threadIdx.x;
    int k0 = g_rowptr[node], k1 = g_rowptr[node + 1];

    float4 acc[NC];
    #pragma unroll
    for (int i = 0; i < NC; i++) acc[i] = make_float4(0.f, 0.f, 0.f, 0.f);

    const int2* ep = (const int2*)g_edge;
    for (int k = k0; k < k1; k++) {
        int2 er = ep[k];
        int src = er.x;
        float w = __int_as_float(er.y);
        const uint2* row = xp + (size_t)src * V;
        #pragma unroll
        for (int i = 0; i < NC; i++) {
            int f = i * 32 + lane;
            if (f < V) {
                uint2 u = row[f];
                float2 v01 = __half22float2(*(const __half2*)&u.x);
                float2 v23 = __half22float2(*(const __half2*)&u.y);
                acc[i].x = fmaf(v01.x, w, acc[i].x);
                acc[i].y = fmaf(v01.y, w, acc[i].y);
                acc[i].z = fmaf(v23.x, w, acc[i].z);
                acc[i].w = fmaf(v23.y, w, acc[i].w);
            }
        }
    }
    #pragma unroll
    for (int i = 0; i < NC; i++) {
        int f = i * 32 + lane;
        if (f < V) {
            uint2 o;
            o.x = f2h2(acc[i].x, acc[i].y);
            o.y = f2h2(acc[i].z, acc[i].w);
            aout[(size_t)node * V + f] = o;
        }
    }
}

// ---------------- fp16 tensor-core GEMM ----------------
#define BM 128
#define BN 64

__device__ __forceinline__ void mma_f16(float* c, const uint32_t* a, const uint32_t* b) {
    asm volatile(
        "mma.sync.aligned.m16n8k16.row.col.f32.f16.f16.f32 "
        "{%0,%1,%2,%3}, {%4,%5,%6,%7}, {%8,%9}, {%0,%1,%2,%3};\n"
        : "+f"(c[0]), "+f"(c[1]), "+f"(c[2]), "+f"(c[3])
        : "r"(a[0]), "r"(a[1]), "r"(a[2]), "r"(a[3]), "r"(b[0]), "r"(b[1]));
}

// A: [M][K2P] uint32 (half pairs, pad=0). B: [N][K2P] uint32 (half pairs, pad=0).
// C: fp16, stride NP halves.
__global__ void __launch_bounds__(256) h_gemm_kernel(
    const uint32_t* __restrict__ A32, const uint32_t* __restrict__ B32,
    const float* __restrict__ bias, uint32_t* __restrict__ C32,
    int M, int N, int NP, int K, int K2P, int relu)
{
    __shared__ uint32_t sA[BM][9];   // 8 half-pairs + pad
    __shared__ uint32_t sB[BN][9];

    int tid = threadIdx.x;
    int warp = tid >> 5, lane = tid & 31;
    int wm = warp >> 1;
    int wn = warp & 1;
    int g = lane >> 2, tg = lane & 3;
    int rowBase = blockIdx.y * BM;
    int colBase = blockIdx.x * BN;

    float acc[2][4][4];
    #pragma unroll
    for (int mt = 0; mt < 2; mt++)
        #pragma unroll
        for (int nt = 0; nt < 4; nt++)
            #pragma unroll
            for (int i = 0; i < 4; i++) acc[mt][nt][i] = 0.0f;

    // loads: A — 2 threads/row, uint4 (8 halves) each; B — threads 0..127, 2/row
    int rowA = tid >> 1;
    int halfA = tid & 1;
    int nB = (tid & 127) >> 1;
    int halfB = tid & 1;
    bool doB = tid < 128;

    bool aok = (rowBase + rowA) < M;
    bool bok = doB && (colBase + nB) < N;
    const uint32_t* Ap = A32 + (size_t)(rowBase + rowA) * K2P + halfA * 4;
    const uint32_t* Bp = B32 + (size_t)(colBase + nB) * K2P + halfB * 4;

    const uint4 z4 = make_uint4(0u, 0u, 0u, 0u);
    uint4 ra, rb;
    ra = aok ? *(const uint4*)(Ap) : z4;
    rb = bok ? *(const uint4*)(Bp) : z4;

    for (int k0 = 0; k0 < K; k0 += 16) {
        __syncthreads();
        int ka = halfA * 4;
        sA[rowA][ka] = ra.x; sA[rowA][ka + 1] = ra.y;
        sA[rowA][ka + 2] = ra.z; sA[rowA][ka + 3] = ra.w;
        if (doB) {
            int kb = halfB * 4;
            sB[nB][kb] = rb.x; sB[nB][kb + 1] = rb.y;
            sB[nB][kb + 2] = rb.z; sB[nB][kb + 3] = rb.w;
        }
        __syncthreads();
        if (k0 + 16 < K) {
            int kp = (k0 + 16) >> 1;
            ra = aok ? *(const uint4*)(Ap + kp) : z4;
            rb = bok ? *(const uint4*)(Bp + kp) : z4;
        }

        uint32_t af[2][4];
        #pragma unroll
        for (int mt = 0; mt < 2; mt++) {
            int r0 = wm * 32 + mt * 16 + g;
            af[mt][0] = sA[r0][tg];     af[mt][1] = sA[r0 + 8][tg];
            af[mt][2] = sA[r0][tg + 4]; af[mt][3] = sA[r0 + 8][tg + 4];
        }
        uint32_t bf[4][2];
        #pragma unroll
        for (int nt = 0; nt < 4; nt++) {
            int n0 = wn * 32 + nt * 8 + g;
            bf[nt][0] = sB[n0][tg]; bf[nt][1] = sB[n0][tg + 4];
        }
        #pragma unroll
        for (int mt = 0; mt < 2; mt++)
            #pragma unroll
            for (int nt = 0; nt < 4; nt++)
                mma_f16(acc[mt][nt], af[mt], bf[nt]);
    }

    #pragma unroll
    for (int mt = 0; mt < 2; mt++) {
        int r0 = rowBase + wm * 32 + mt * 16 + g;
        #pragma unroll
        for (int nt = 0; nt < 4; nt++) {
            int c0 = colBase + wn * 32 + nt * 8 + tg * 2;
            #pragma unroll
            for (int half = 0; half < 2; half++) {
                int r = r0 + half * 8;
                if (r >= M || c0 >= N) continue;
                float v0 = acc[mt][nt][half * 2 + 0] + bias[c0];
                float v1 = acc[mt][nt][half * 2 + 1] + bias[c0 + 1];
                if (relu) { v0 = fmaxf(v0, 0.0f); v1 = fmaxf(v1, 0.0f); }
                C32[((size_t)r * NP + c0) >> 1] = f2h2(v0, v1);
            }
        }
    }
}

// ---------------- segmented global max pool (fp16 in/out) ----------------
__global__ void pool_kernel(const uint16_t* __restrict__ y)
{
    int grp = blockIdx.x * blockDim.y + threadIdx.y;
    if (grp >= N_GRAPHS) return;
    int c = blockIdx.y * 32 + threadIdx.x;
    if (c >= F3) return;
    int s = g_gstart[grp], e = g_gstart[grp + 1];
    float m = 0.0f;
    for (int i = s; i < e; i++)
        m = fmaxf(m, __half2float(__ushort_as_half(y[(size_t)i * FP3 + c])));
    g_p[(size_t)grp * FP3 + c] = f2h(m);
}

// ---------------- final 512 -> 1 dot + sigmoid ----------------
__global__ void final_kernel(const float* __restrict__ Wo,
                             const float* __restrict__ bo, float* __restrict__ out)
{
    int row = blockIdx.x * blockDim.y + threadIdx.y;
    if (row >= N_GRAPHS) return;
    int lane = threadIdx.x;
    float s = 0.0f;
    for (int k = lane; k < 512; k += 32)
        s = fmaf(__half2float(__ushort_as_half(g_m2[(size_t)row * 512 + k])), Wo[k], s);
    #pragma unroll
    for (int o = 16; o; o >>= 1) s += __shfl_xor_sync(0xFFFFFFFFu, s, o);
    if (lane == 0) out[row] = 1.0f / (1.0f + expf(-(s + bo[0])));
}

// ---------------- launch ----------------
extern "C" void kernel_launch(void* const* d_in, const int* in_sizes, int n_in,
                              void* d_out, int out_size)
{
    const float* x     = (const float*)d_in[0];
    const int*   ei    = (const int*)d_in[1];
    const int*   batch = (const int*)d_in[2];
    const float* W1 = (const float*)d_in[3];  const float* b1 = (const float*)d_in[4];
    const float* W2 = (const float*)d_in[5];  const float* b2 = (const float*)d_in[6];
    const float* W3 = (const float*)d_in[7];  const float* b3 = (const float*)d_in[8];
    const float* Wg1 = (const float*)d_in[9];  const float* bg1 = (const float*)d_in[10];
    const float* Wg2 = (const float*)d_in[11]; const float* bg2 = (const float*)d_in[12];
    const float* Wf1 = (const float*)d_in[13]; const float* bf1 = (const float*)d_in[14];
    const float* Wf2 = (const float*)d_in[15]; const float* bf2 = (const float*)d_in[16];
    const float* Wo  = (const float*)d_in[17]; const float* bo  = (const float*)d_in[18];
    float* out = (float*)d_out;

    uint16_t *xp, *a, *w, *y1, *y2, *y3, *p, *m1, *m2;
    cudaGetSymbolAddress((void**)&xp, g_xp);
    cudaGetSymbolAddress((void**)&a,  g_a);
    cudaGetSymbolAddress((void**)&w,  g_w);
    cudaGetSymbolAddress((void**)&y1, g_y1);
    cudaGetSymbolAddress((void**)&y2, g_y2);
    cudaGetSymbolAddress((void**)&y3, g_y3);
    cudaGetSymbolAddress((void**)&p,  g_p);
    cudaGetSymbolAddress((void**)&m1, g_m1);
    cudaGetSymbolAddress((void**)&m2, g_m2);

    // preprocessing: 4 launches
    prep_kernel<<<(PREP_TOT + 255) / 256, 256>>>(ei, batch, x, W1, W2, W3, Wg1, Wg2, Wf1, Wf2);
    scan_p1_kernel<<<SCAN_NB, 256>>>();
    scan_p3_kernel<<<SCAN_NB, 256>>>();
    fill_kernel<<<(NE_TOT + N_NODES + 1 + 255) / 256, 256>>>(ei);

    auto gemm = [&](const uint16_t* A, int woff, const float* bias, uint16_t* C,
                    int M, int N, int NP, int K, int K2P, int relu) {
        dim3 grid((N + BN - 1) / BN, (M + BM - 1) / BM);
        h_gemm_kernel<<<grid, 256>>>((const uint32_t*)A, (const uint32_t*)(w + woff),
                                     bias, (uint32_t*)C, M, N, NP, K, K2P, relu);
    };
    dim3 cb(32, 8);

    // layer 1: gather xp (V=20) -> a -> GEMM -> y1 (pad 80)
    agg_kernel_h<20><<<(N_NODES + 7) / 8, cb>>>((const uint2*)xp, (uint2*)a);
    gemm(a, OW1, b1, y1, N_NODES, F1, FP0, F0, FP0 / 2, 1);
    // layer 2: gather y1 (V=20) -> a -> GEMM -> y2 (pad 160)
    agg_kernel_h<20><<<(N_NODES + 7) / 8, cb>>>((const uint2*)y1, (uint2*)a);
    gemm(a, OW2, b2, y2, N_NODES, F2, FP2, F1, FP0 / 2, 1);
    // layer 3: gather y2 (V=40) -> a -> GEMM -> y3 (pad 320)
    agg_kernel_h<40><<<(N_NODES + 7) / 8, cb>>>((const uint2*)y2, (uint2*)a);
    gemm(a, OW3, b3, y3, N_NODES, F3, FP3, F2, FP2 / 2, 1);

    // pool
    pool_kernel<<<dim3((N_GRAPHS + 7) / 8, (F3 + 31) / 32), cb>>>(y3);

    // MLP head (all fp16 storage, fp32 accumulate)
    gemm(p,  OWG1, bg1, m1, N_GRAPHS, 1024, 1024, F3,   FP3 / 2,  1);
    gemm(m1, OWG2, bg2, m2, N_GRAPHS, 128,  128,  1024, 512,      0);
    gemm(m2, OWF1, bf1, m1, N_GRAPHS, 1024, 1024, 128,  64,       1);
    gemm(m1, OWF2, bf2, m2, N_GRAPHS, 512,  512,  1024, 512,      1);
    final_kernel<<<(N_GRAPHS + 7) / 8, cb>>>(Wo, bo, out);
}